// round 7
// baseline (speedup 1.0000x reference)
#include <cuda_runtime.h>
#include <cstdint>

// Problem constants (fixed by the reference)
#define NBF   64          // NUM_BEV_FEATURES (channels)
#define GNX   512
#define GNY   512
#define GNZ   1
#define NBATCH 4
#define CELLS_PER_B (GNZ * GNY * GNX)          // 262144
#define TOTAL_CELLS (NBATCH * CELLS_PER_B)     // 1048576

// cell -> pillar index map (4 MB). __device__ global: allowed scratch.
__device__ int g_cell2pillar[TOTAL_CELLS];

// ---------------------------------------------------------------------------
// Kernel 1: fill index map with -1 (vectorized, 4 MB write)
// ---------------------------------------------------------------------------
__global__ void fill_idx_kernel() {
    int i = blockIdx.x * blockDim.x + threadIdx.x;   // 0 .. TOTAL_CELLS/4 - 1
    int4* p = reinterpret_cast<int4*>(g_cell2pillar);
    p[i] = make_int4(-1, -1, -1, -1);
}

// ---------------------------------------------------------------------------
// Kernel 2: scatter pillar id into the cell map
// coords: [P, 4] int32 rows (b, z, y, x)  -- JAX x64-disabled downcasts int64
// ---------------------------------------------------------------------------
__global__ void scatter_idx_kernel(const int* __restrict__ coords, int P) {
    int p = blockIdx.x * blockDim.x + threadIdx.x;
    if (p < P) {
        int4 c = reinterpret_cast<const int4*>(coords)[p];  // (b, z, y, x)
        // reference: cell = z + y*NX + x
        long long cell = (long long)c.y + (long long)c.z * GNX + (long long)c.w;
        long long idx  = (long long)c.x * CELLS_PER_B + cell;
        if (idx >= 0 && idx < TOTAL_CELLS)
            g_cell2pillar[idx] = p;
    }
}

// ---------------------------------------------------------------------------
// Kernel 3: fused zero + gather + transpose + write.
// Grid: (GNX/64, GNY, NBATCH), 256 threads.
// Each block produces out[b, 0..63, y, x0..x0+63]  (64 ch x 64 x = 16 KB).
// smem tile layout: s[c*65 + x]  (stride 65 -> conflict-free column writes)
// ---------------------------------------------------------------------------
__global__ __launch_bounds__(256) void scatter_out_kernel(
    const float* __restrict__ feat,   // [P, 64]
    float* __restrict__ out)          // [B, 64, 512, 512]
{
    __shared__ float s[NBF * 65];     // 16640 B
    __shared__ int   sp[64];

    const int t  = threadIdx.x;
    const int b  = blockIdx.z;
    const int y  = blockIdx.y;
    const int x0 = blockIdx.x * 64;

    // load cell->pillar for this x-tile
    if (t < 64)
        sp[t] = g_cell2pillar[b * CELLS_PER_B + y * GNX + x0 + t];

    // zero the smem tile (covers unoccupied cells)
    #pragma unroll
    for (int i = t; i < NBF * 65; i += 256)
        s[i] = 0.0f;
    __syncthreads();

    // gather phase: 4 groups of 64 threads, each group one cell per iter.
    // feat row read is a contiguous 256 B coalesced load.
    // smem store s[c*65 + j]: lanes vary c -> banks (65c)%32 = c%32, conflict-free.
    {
        const int c = t & 63;
        const int g = t >> 6;
        #pragma unroll
        for (int j = g; j < 64; j += 4) {
            int p = sp[j];
            if (p >= 0)
                s[c * 65 + j] = feat[(size_t)p * NBF + c];
        }
    }
    __syncthreads();

    // write phase: thread t -> xq = t%16 (x quad), cb = t/16 (channel base).
    // Each 16-thread group writes a contiguous 256 B float4 run per channel.
    {
        const int xq = t & 15;
        const int cb = t >> 4;                 // 0..15
        const size_t plane = (size_t)GNY * GNX;   // 262144
        float* outp = out + (((size_t)b * NBF) * GNY + y) * GNX + x0 + 4 * xq;
        #pragma unroll
        for (int ci = 0; ci < 4; ci++) {
            int cc = cb + 16 * ci;             // channel
            int sbase = cc * 65 + 4 * xq;
            float4 v;
            v.x = s[sbase + 0];
            v.y = s[sbase + 1];
            v.z = s[sbase + 2];
            v.w = s[sbase + 3];
            *reinterpret_cast<float4*>(outp + (size_t)cc * plane) = v;
        }
    }
}

// ---------------------------------------------------------------------------
// Launch
// ---------------------------------------------------------------------------
extern "C" void kernel_launch(void* const* d_in, const int* in_sizes, int n_in,
                              void* d_out, int out_size)
{
    const float* feat   = (const float*)d_in[0];   // [P, 64] fp32
    const int*   coords = (const int*)d_in[1];     // [P, 4] int32
    (void)n_in; (void)out_size;

    const int P = in_sizes[0] / NBF;               // 120000

    // 1) reset index map
    fill_idx_kernel<<<(TOTAL_CELLS / 4 + 255) / 256, 256>>>();

    // 2) scatter pillar ids
    scatter_idx_kernel<<<(P + 255) / 256, 256>>>(coords, P);

    // 3) fused zero + gather-transpose + coalesced write
    dim3 grid(GNX / 64, GNY, NBATCH);
    scatter_out_kernel<<<grid, 256>>>(feat, (float*)d_out);
}